// round 1
// baseline (speedup 1.0000x reference)
#include <cuda_runtime.h>
#include <math.h>

#define NFEAT  256
#define NHID   128
#define NCLASS 40
#define MAXN   100000

// Scratch (allocation-free: __device__ globals). ~134 MB total.
__device__ __align__(256) float g_H0p[MAXN * NHID];   // x @ W0
__device__ __align__(256) float g_H1 [MAXN * NHID];   // spmm accum -> normalized relu (in place)
__device__ __align__(256) float g_Z2p[MAXN * NCLASS]; // H1 @ W1
__device__ __align__(256) float g_Z2a[MAXN * NCLASS]; // spmm accum

// ---------------------------------------------------------------------------
// GEMM1: C[M,128] = A[M,256] @ B[256,128]. Classic 128x128 tile, BK=8, 8x8/thread.
// ---------------------------------------------------------------------------
__global__ __launch_bounds__(256) void gemm1_kernel(
    const float* __restrict__ A, const float* __restrict__ B,
    float* __restrict__ C, int M)
{
    __shared__ float As[8][128];
    __shared__ float Bs[8][128];

    int t = threadIdx.x;
    int blockRow = blockIdx.x * 128;

    int tx = t & 15;        // 0..15 -> 8 cols each
    int ty = t >> 4;        // 0..15 -> 8 rows each

    int aRow = t >> 1;          // 0..127
    int aCol = (t & 1) * 4;     // 0 or 4
    int bRow = t >> 5;          // 0..7
    int bCol = (t & 31) * 4;    // 0..124

    float acc[8][8];
#pragma unroll
    for (int i = 0; i < 8; i++)
#pragma unroll
        for (int j = 0; j < 8; j++) acc[i][j] = 0.f;

    for (int k0 = 0; k0 < NFEAT; k0 += 8) {
        int gr = blockRow + aRow;
        float4 av = make_float4(0.f, 0.f, 0.f, 0.f);
        if (gr < M) av = *(const float4*)(A + (size_t)gr * NFEAT + k0 + aCol);
        As[aCol + 0][aRow] = av.x;
        As[aCol + 1][aRow] = av.y;
        As[aCol + 2][aRow] = av.z;
        As[aCol + 3][aRow] = av.w;

        float4 bv = *(const float4*)(B + (size_t)(k0 + bRow) * NHID + bCol);
        *(float4*)&Bs[bRow][bCol] = bv;

        __syncthreads();

#pragma unroll
        for (int k = 0; k < 8; k++) {
            float4 a0 = *(float4*)&As[k][ty * 8];
            float4 a1 = *(float4*)&As[k][ty * 8 + 4];
            float4 b0 = *(float4*)&Bs[k][tx * 8];
            float4 b1 = *(float4*)&Bs[k][tx * 8 + 4];
            float ar[8] = {a0.x, a0.y, a0.z, a0.w, a1.x, a1.y, a1.z, a1.w};
            float br[8] = {b0.x, b0.y, b0.z, b0.w, b1.x, b1.y, b1.z, b1.w};
#pragma unroll
            for (int i = 0; i < 8; i++)
#pragma unroll
                for (int j = 0; j < 8; j++)
                    acc[i][j] = fmaf(ar[i], br[j], acc[i][j]);
        }
        __syncthreads();
    }

#pragma unroll
    for (int i = 0; i < 8; i++) {
        int gr = blockRow + ty * 8 + i;
        if (gr < M) {
            float4 v0 = make_float4(acc[i][0], acc[i][1], acc[i][2], acc[i][3]);
            float4 v1 = make_float4(acc[i][4], acc[i][5], acc[i][6], acc[i][7]);
            *(float4*)(C + (size_t)gr * NHID + tx * 8)     = v0;
            *(float4*)(C + (size_t)gr * NHID + tx * 8 + 4) = v1;
        }
    }
}

// ---------------------------------------------------------------------------
// SPMM1: Hout[dst] += w * Hin[src], 128 feats. One warp per edge, float4/lane,
// vector reduction red.global.add.v4.f32.
// ---------------------------------------------------------------------------
__global__ __launch_bounds__(256) void spmm1_kernel(
    const int* __restrict__ src, const int* __restrict__ dst,
    const float* __restrict__ w,
    const float* __restrict__ Hin, float* __restrict__ Hout, int E)
{
    int gid = blockIdx.x * blockDim.x + threadIdx.x;
    int e = gid >> 5;
    if (e >= E) return;
    int lane = gid & 31;

    int s = __ldg(src + e);
    int d = __ldg(dst + e);
    float wt = __ldg(w + e);

    float4 v = *(const float4*)(Hin + (size_t)s * NHID + lane * 4);
    float a = v.x * wt, b = v.y * wt, c = v.z * wt, dd = v.w * wt;

    float* p = Hout + (size_t)d * NHID + lane * 4;
    asm volatile("red.global.add.v4.f32 [%0], {%1,%2,%3,%4};"
                 :: "l"(p), "f"(a), "f"(b), "f"(c), "f"(dd) : "memory");
}

// ---------------------------------------------------------------------------
// Bias + L2 normalize + ReLU, in place. One warp per node.
// ---------------------------------------------------------------------------
__global__ __launch_bounds__(256) void norm_kernel(
    float* __restrict__ H, const float* __restrict__ b0, int M)
{
    int gid = blockIdx.x * blockDim.x + threadIdx.x;
    int node = gid >> 5;
    if (node >= M) return;
    int lane = gid & 31;

    float4 v = *(float4*)(H + (size_t)node * NHID + lane * 4);
    float4 b = *(const float4*)(b0 + lane * 4);
    v.x += b.x; v.y += b.y; v.z += b.z; v.w += b.w;

    float ss = v.x * v.x + v.y * v.y + v.z * v.z + v.w * v.w;
#pragma unroll
    for (int off = 16; off > 0; off >>= 1)
        ss += __shfl_xor_sync(0xffffffffu, ss, off);

    float nrm = sqrtf(ss);
    float scale = 1.0f / fmaxf(nrm, 1e-12f);

    v.x = fmaxf(v.x * scale, 0.f);
    v.y = fmaxf(v.y * scale, 0.f);
    v.z = fmaxf(v.z * scale, 0.f);
    v.w = fmaxf(v.w * scale, 0.f);
    *(float4*)(H + (size_t)node * NHID + lane * 4) = v;
}

// ---------------------------------------------------------------------------
// GEMM2: Z[M,40] = H[M,128] @ W[128,40]. 128 nodes/block, K split in halves
// to stay under 48 KB static smem. Thread = (ng 0..31, cg 0..7):
// nodes {ng, ng+32, ng+64, ng+96}, classes {5cg..5cg+4}.
// ---------------------------------------------------------------------------
__global__ __launch_bounds__(256) void gemm2_kernel(
    const float* __restrict__ H, const float* __restrict__ W,
    float* __restrict__ Z, int M)
{
    __shared__ float hs[128][65];   // [node][k] pad->conflict-free (stride%32==1)
    __shared__ float ws[64][NCLASS];

    int t = threadIdx.x;
    int node0 = blockIdx.x * 128;
    int ng = t & 31, cg = t >> 5;

    float acc[4][5];
#pragma unroll
    for (int i = 0; i < 4; i++)
#pragma unroll
        for (int j = 0; j < 5; j++) acc[i][j] = 0.f;

#pragma unroll
    for (int h = 0; h < 2; h++) {
        int k0 = h * 64;
        for (int i = t; i < 64 * NCLASS; i += 256)
            ws[i / NCLASS][i % NCLASS] = W[(size_t)(k0 + i / NCLASS) * NCLASS + i % NCLASS];

        for (int i = t * 4; i < 128 * 64; i += 256 * 4) {
            int node = i >> 6, k = i & 63;
            int gn = node0 + node;
            float4 v = make_float4(0.f, 0.f, 0.f, 0.f);
            if (gn < M) v = *(const float4*)(H + (size_t)gn * NHID + k0 + k);
            hs[node][k + 0] = v.x;
            hs[node][k + 1] = v.y;
            hs[node][k + 2] = v.z;
            hs[node][k + 3] = v.w;
        }
        __syncthreads();

#pragma unroll 4
        for (int k = 0; k < 64; k++) {
            float b[5];
#pragma unroll
            for (int j = 0; j < 5; j++) b[j] = ws[k][cg * 5 + j];  // broadcast
#pragma unroll
            for (int i = 0; i < 4; i++) {
                float a = hs[ng + 32 * i][k];                       // conflict-free
#pragma unroll
                for (int j = 0; j < 5; j++)
                    acc[i][j] = fmaf(a, b[j], acc[i][j]);
            }
        }
        __syncthreads();
    }

#pragma unroll
    for (int i = 0; i < 4; i++) {
        int gn = node0 + ng + 32 * i;
        if (gn < M)
#pragma unroll
            for (int j = 0; j < 5; j++)
                Z[(size_t)gn * NCLASS + cg * 5 + j] = acc[i][j];
    }
}

// ---------------------------------------------------------------------------
// SPMM2: 40 feats = 10 float4 chunks per edge. Thread = (edge, chunk).
// ---------------------------------------------------------------------------
__global__ __launch_bounds__(256) void spmm2_kernel(
    const int* __restrict__ src, const int* __restrict__ dst,
    const float* __restrict__ w,
    const float* __restrict__ Zin, float* __restrict__ Zout, int E)
{
    int gid = blockIdx.x * blockDim.x + threadIdx.x;
    int e = gid / 10;
    if (e >= E) return;
    int c = gid - e * 10;

    int s = __ldg(src + e);
    int d = __ldg(dst + e);
    float wt = __ldg(w + e);

    float4 v = *(const float4*)(Zin + (size_t)s * NCLASS + c * 4);
    float a = v.x * wt, b = v.y * wt, cc = v.z * wt, dd = v.w * wt;

    float* p = Zout + (size_t)d * NCLASS + c * 4;
    asm volatile("red.global.add.v4.f32 [%0], {%1,%2,%3,%4};"
                 :: "l"(p), "f"(a), "f"(b), "f"(cc), "f"(dd) : "memory");
}

// ---------------------------------------------------------------------------
// Bias + log_softmax over 40 classes. One warp per node; lane covers class
// {lane} and (lane<8) {lane+32}.
// ---------------------------------------------------------------------------
__global__ __launch_bounds__(256) void lsm_kernel(
    const float* __restrict__ Z, const float* __restrict__ b1,
    float* __restrict__ out, int M)
{
    int gid = blockIdx.x * blockDim.x + threadIdx.x;
    int node = gid >> 5;
    if (node >= M) return;
    int lane = gid & 31;

    const float* zr = Z + (size_t)node * NCLASS;
    float z0 = zr[lane] + __ldg(b1 + lane);
    float z1 = -INFINITY;
    if (lane < 8) z1 = zr[32 + lane] + __ldg(b1 + 32 + lane);

    float m = fmaxf(z0, z1);
#pragma unroll
    for (int off = 16; off > 0; off >>= 1)
        m = fmaxf(m, __shfl_xor_sync(0xffffffffu, m, off));

    float es = expf(z0 - m) + ((lane < 8) ? expf(z1 - m) : 0.f);
#pragma unroll
    for (int off = 16; off > 0; off >>= 1)
        es += __shfl_xor_sync(0xffffffffu, es, off);

    float lse = logf(es);
    float* orow = out + (size_t)node * NCLASS;
    orow[lane] = z0 - m - lse;
    if (lane < 8) orow[32 + lane] = z1 - m - lse;
}

// ---------------------------------------------------------------------------
extern "C" void kernel_launch(void* const* d_in, const int* in_sizes, int n_in,
                              void* d_out, int out_size)
{
    const float* x    = (const float*)d_in[0];
    const int*   esrc = (const int*)  d_in[1];
    const int*   edst = (const int*)  d_in[2];
    const float* ew   = (const float*)d_in[3];
    const float* W0   = (const float*)d_in[4];
    const float* b0   = (const float*)d_in[5];
    const float* W1   = (const float*)d_in[6];
    const float* b1   = (const float*)d_in[7];
    float* out = (float*)d_out;

    int M = in_sizes[0] / NFEAT;   // 100000
    int E = in_sizes[1];           // 3200000

    float *H0p, *H1, *Z2p, *Z2a;
    cudaGetSymbolAddress((void**)&H0p, g_H0p);
    cudaGetSymbolAddress((void**)&H1,  g_H1);
    cudaGetSymbolAddress((void**)&Z2p, g_Z2p);
    cudaGetSymbolAddress((void**)&Z2a, g_Z2a);

    cudaMemsetAsync(H1,  0, (size_t)M * NHID   * sizeof(float), 0);
    cudaMemsetAsync(Z2a, 0, (size_t)M * NCLASS * sizeof(float), 0);

    // Layer 1 dense projection
    gemm1_kernel<<<(M + 127) / 128, 256>>>(x, W0, H0p, M);

    // SPMM1: warp/edge
    {
        long long threads = (long long)E * 32;
        int blocks = (int)((threads + 255) / 256);
        spmm1_kernel<<<blocks, 256>>>(esrc, edst, ew, H0p, H1, E);
    }

    // bias + l2norm + relu
    {
        long long threads = (long long)M * 32;
        int blocks = (int)((threads + 255) / 256);
        norm_kernel<<<blocks, 256>>>(H1, b0, M);
    }

    // Layer 2 dense projection
    gemm2_kernel<<<(M + 127) / 128, 256>>>(H1, W1, Z2p, M);

    // SPMM2: 10 chunks/edge
    {
        long long threads = (long long)E * 10;
        int blocks = (int)((threads + 255) / 256);
        spmm2_kernel<<<blocks, 256>>>(esrc, edst, ew, Z2p, Z2a, E);
    }

    // bias + log_softmax
    {
        long long threads = (long long)M * 32;
        int blocks = (int)((threads + 255) / 256);
        lsm_kernel<<<blocks, 256>>>(Z2a, b1, out, M);
    }
}

// round 2
// speedup vs baseline: 1.1807x; 1.1807x over previous
#include <cuda_runtime.h>
#include <math.h>

#define NFEAT  256
#define NHID   128
#define NCLASS 40
#define MAXN   100000
#define MAXE   3200000

// Scratch (allocation-free: __device__ globals).
__device__ __align__(256) float g_H0p[MAXN * NHID];   // x @ W0
__device__ __align__(256) float g_H1 [MAXN * NHID];   // normalized relu hidden
__device__ __align__(256) float g_Z2p[MAXN * NCLASS]; // H1 @ W1
__device__ __align__(256) int   g_cnt[MAXN];          // per-dst degree histogram
__device__ __align__(256) int   g_rowstart[MAXN + 1]; // CSR row pointers
__device__ __align__(256) int   g_cursor[MAXN];       // scatter cursors
__device__ __align__(256) int2  g_edges[MAXE];        // CSR payload: {src, w bits}

// ---------------------------------------------------------------------------
// CSR build step 1: histogram of destination nodes.
// ---------------------------------------------------------------------------
__global__ __launch_bounds__(256) void hist_kernel(
    const int* __restrict__ dst, int E)
{
    int e = blockIdx.x * blockDim.x + threadIdx.x;
    if (e < E) atomicAdd(&g_cnt[__ldg(dst + e)], 1);
}

// ---------------------------------------------------------------------------
// CSR build step 2: exclusive prefix sum over N counts. Single block, 1024 thr.
// Each thread owns a contiguous chunk; block-scan chunk sums; write rowstart
// and initialize cursor.
// ---------------------------------------------------------------------------
__global__ __launch_bounds__(1024) void scan_kernel(int N)
{
    __shared__ int s[1024];
    int t = threadIdx.x;
    int chunk = (N + 1023) / 1024;
    int beg = t * chunk;
    int end = min(beg + chunk, N);

    int sum = 0;
    for (int i = beg; i < end; i++) sum += g_cnt[i];
    s[t] = sum;
    __syncthreads();

    // inclusive Hillis-Steele scan
#pragma unroll
    for (int off = 1; off < 1024; off <<= 1) {
        int v = (t >= off) ? s[t - off] : 0;
        __syncthreads();
        s[t] += v;
        __syncthreads();
    }

    int base = s[t] - sum;   // exclusive prefix
    for (int i = beg; i < end; i++) {
        g_rowstart[i] = base;
        g_cursor[i]   = base;
        base += g_cnt[i];
    }
    if (t == 1023) g_rowstart[N] = s[1023];
}

// ---------------------------------------------------------------------------
// CSR build step 3: scatter (src, w) into per-dst segments.
// ---------------------------------------------------------------------------
__global__ __launch_bounds__(256) void scatter_kernel(
    const int* __restrict__ src, const int* __restrict__ dst,
    const float* __restrict__ w, int E)
{
    int e = blockIdx.x * blockDim.x + threadIdx.x;
    if (e >= E) return;
    int d = __ldg(dst + e);
    int pos = atomicAdd(&g_cursor[d], 1);
    g_edges[pos] = make_int2(__ldg(src + e), __float_as_int(__ldg(w + e)));
}

// ---------------------------------------------------------------------------
// GEMM1: C[M,128] = A[M,256] @ B[256,128]. 128x128 tile, BK=8, 8x8/thread.
// ---------------------------------------------------------------------------
__global__ __launch_bounds__(256) void gemm1_kernel(
    const float* __restrict__ A, const float* __restrict__ B,
    float* __restrict__ C, int M)
{
    __shared__ float As[8][128];
    __shared__ float Bs[8][128];

    int t = threadIdx.x;
    int blockRow = blockIdx.x * 128;

    int tx = t & 15;
    int ty = t >> 4;

    int aRow = t >> 1;
    int aCol = (t & 1) * 4;
    int bRow = t >> 5;
    int bCol = (t & 31) * 4;

    float acc[8][8];
#pragma unroll
    for (int i = 0; i < 8; i++)
#pragma unroll
        for (int j = 0; j < 8; j++) acc[i][j] = 0.f;

    for (int k0 = 0; k0 < NFEAT; k0 += 8) {
        int gr = blockRow + aRow;
        float4 av = make_float4(0.f, 0.f, 0.f, 0.f);
        if (gr < M) av = *(const float4*)(A + (size_t)gr * NFEAT + k0 + aCol);
        As[aCol + 0][aRow] = av.x;
        As[aCol + 1][aRow] = av.y;
        As[aCol + 2][aRow] = av.z;
        As[aCol + 3][aRow] = av.w;

        float4 bv = *(const float4*)(B + (size_t)(k0 + bRow) * NHID + bCol);
        *(float4*)&Bs[bRow][bCol] = bv;

        __syncthreads();

#pragma unroll
        for (int k = 0; k < 8; k++) {
            float4 a0 = *(float4*)&As[k][ty * 8];
            float4 a1 = *(float4*)&As[k][ty * 8 + 4];
            float4 b0 = *(float4*)&Bs[k][tx * 8];
            float4 b1 = *(float4*)&Bs[k][tx * 8 + 4];
            float ar[8] = {a0.x, a0.y, a0.z, a0.w, a1.x, a1.y, a1.z, a1.w};
            float br[8] = {b0.x, b0.y, b0.z, b0.w, b1.x, b1.y, b1.z, b1.w};
#pragma unroll
            for (int i = 0; i < 8; i++)
#pragma unroll
                for (int j = 0; j < 8; j++)
                    acc[i][j] = fmaf(ar[i], br[j], acc[i][j]);
        }
        __syncthreads();
    }

#pragma unroll
    for (int i = 0; i < 8; i++) {
        int gr = blockRow + ty * 8 + i;
        if (gr < M) {
            float4 v0 = make_float4(acc[i][0], acc[i][1], acc[i][2], acc[i][3]);
            float4 v1 = make_float4(acc[i][4], acc[i][5], acc[i][6], acc[i][7]);
            *(float4*)(C + (size_t)gr * NHID + tx * 8)     = v0;
            *(float4*)(C + (size_t)gr * NHID + tx * 8 + 4) = v1;
        }
    }
}

// ---------------------------------------------------------------------------
// Fused SPMM1 + bias + L2 normalize + ReLU. Warp per dst node, CSR gather,
// register accumulation (no atomics).
// ---------------------------------------------------------------------------
__global__ __launch_bounds__(256) void spmm1norm_kernel(
    const float* __restrict__ Hin, const float* __restrict__ b0,
    float* __restrict__ Hout, int M)
{
    int gid = blockIdx.x * blockDim.x + threadIdx.x;
    int node = gid >> 5;
    if (node >= M) return;
    int lane = gid & 31;

    int beg = __ldg(&g_rowstart[node]);
    int end = __ldg(&g_rowstart[node + 1]);

    float4 a0 = make_float4(0.f, 0.f, 0.f, 0.f);
    float4 a1 = make_float4(0.f, 0.f, 0.f, 0.f);

    int i = beg;
    for (; i + 1 < end; i += 2) {
        int2 e0 = __ldg(&g_edges[i]);
        int2 e1 = __ldg(&g_edges[i + 1]);
        float4 v0 = *(const float4*)(Hin + (size_t)e0.x * NHID + lane * 4);
        float4 v1 = *(const float4*)(Hin + (size_t)e1.x * NHID + lane * 4);
        float w0 = __int_as_float(e0.y);
        float w1 = __int_as_float(e1.y);
        a0.x = fmaf(w0, v0.x, a0.x); a0.y = fmaf(w0, v0.y, a0.y);
        a0.z = fmaf(w0, v0.z, a0.z); a0.w = fmaf(w0, v0.w, a0.w);
        a1.x = fmaf(w1, v1.x, a1.x); a1.y = fmaf(w1, v1.y, a1.y);
        a1.z = fmaf(w1, v1.z, a1.z); a1.w = fmaf(w1, v1.w, a1.w);
    }
    if (i < end) {
        int2 e0 = __ldg(&g_edges[i]);
        float4 v0 = *(const float4*)(Hin + (size_t)e0.x * NHID + lane * 4);
        float w0 = __int_as_float(e0.y);
        a0.x = fmaf(w0, v0.x, a0.x); a0.y = fmaf(w0, v0.y, a0.y);
        a0.z = fmaf(w0, v0.z, a0.z); a0.w = fmaf(w0, v0.w, a0.w);
    }

    float4 v;
    float4 b = *(const float4*)(b0 + lane * 4);
    v.x = a0.x + a1.x + b.x;
    v.y = a0.y + a1.y + b.y;
    v.z = a0.z + a1.z + b.z;
    v.w = a0.w + a1.w + b.w;

    float ss = v.x * v.x + v.y * v.y + v.z * v.z + v.w * v.w;
#pragma unroll
    for (int off = 16; off > 0; off >>= 1)
        ss += __shfl_xor_sync(0xffffffffu, ss, off);

    float scale = 1.0f / fmaxf(sqrtf(ss), 1e-12f);

    v.x = fmaxf(v.x * scale, 0.f);
    v.y = fmaxf(v.y * scale, 0.f);
    v.z = fmaxf(v.z * scale, 0.f);
    v.w = fmaxf(v.w * scale, 0.f);
    *(float4*)(Hout + (size_t)node * NHID + lane * 4) = v;
}

// ---------------------------------------------------------------------------
// GEMM2: Z[M,40] = H[M,128] @ W[128,40]. Vectorized LDS.128 both operands.
// pad-68 layout -> conflict-free. Thread = (ng 0..31, cg 0..7): nodes
// {ng,+32,+64,+96}, classes {5cg..5cg+4}.
// ---------------------------------------------------------------------------
__global__ __launch_bounds__(256) void gemm2_kernel(
    const float* __restrict__ H, const float* __restrict__ W,
    float* __restrict__ Z, int M)
{
    __shared__ float hs[128][68];   // [node][k], stride%32==4 -> LDS.128 conflict-free
    __shared__ float wsT[40][68];   // [class][k] transposed, broadcast LDS.128

    int t = threadIdx.x;
    int node0 = blockIdx.x * 128;
    int ng = t & 31, cg = t >> 5;

    float acc[4][5];
#pragma unroll
    for (int i = 0; i < 4; i++)
#pragma unroll
        for (int j = 0; j < 5; j++) acc[i][j] = 0.f;

#pragma unroll
    for (int h = 0; h < 2; h++) {
        int k0 = h * 64;
        for (int i = t; i < 64 * NCLASS; i += 256) {
            int k = i & 63, c = i >> 6;
            wsT[c][k] = W[(size_t)(k0 + k) * NCLASS + c];
        }

        for (int i = t * 4; i < 128 * 64; i += 256 * 4) {
            int node = i >> 6, k = i & 63;
            int gn = node0 + node;
            float4 v = make_float4(0.f, 0.f, 0.f, 0.f);
            if (gn < M) v = *(const float4*)(H + (size_t)gn * NHID + k0 + k);
            hs[node][k + 0] = v.x;
            hs[node][k + 1] = v.y;
            hs[node][k + 2] = v.z;
            hs[node][k + 3] = v.w;
        }
        __syncthreads();

#pragma unroll 4
        for (int k = 0; k < 64; k += 4) {
            float4 b[5];
#pragma unroll
            for (int j = 0; j < 5; j++) b[j] = *(float4*)&wsT[cg * 5 + j][k];
#pragma unroll
            for (int i = 0; i < 4; i++) {
                float4 a = *(float4*)&hs[ng + 32 * i][k];
#pragma unroll
                for (int j = 0; j < 5; j++) {
                    acc[i][j] = fmaf(a.x, b[j].x, acc[i][j]);
                    acc[i][j] = fmaf(a.y, b[j].y, acc[i][j]);
                    acc[i][j] = fmaf(a.z, b[j].z, acc[i][j]);
                    acc[i][j] = fmaf(a.w, b[j].w, acc[i][j]);
                }
            }
        }
        __syncthreads();
    }

#pragma unroll
    for (int i = 0; i < 4; i++) {
        int gn = node0 + ng + 32 * i;
        if (gn < M)
#pragma unroll
            for (int j = 0; j < 5; j++)
                Z[(size_t)gn * NCLASS + cg * 5 + j] = acc[i][j];
    }
}

// ---------------------------------------------------------------------------
// Fused SPMM2 + bias + log_softmax. Warp per dst node, CSR gather.
// Lane covers class {lane} and (lane<8) {lane+32}.
// ---------------------------------------------------------------------------
__global__ __launch_bounds__(256) void spmm2lsm_kernel(
    const float* __restrict__ Zin, const float* __restrict__ b1,
    float* __restrict__ out, int M)
{
    int gid = blockIdx.x * blockDim.x + threadIdx.x;
    int node = gid >> 5;
    if (node >= M) return;
    int lane = gid & 31;

    int beg = __ldg(&g_rowstart[node]);
    int end = __ldg(&g_rowstart[node + 1]);

    float z0a = 0.f, z0b = 0.f, z1a = 0.f, z1b = 0.f;

    int i = beg;
    for (; i + 1 < end; i += 2) {
        int2 e0 = __ldg(&g_edges[i]);
        int2 e1 = __ldg(&g_edges[i + 1]);
        float w0 = __int_as_float(e0.y);
        float w1 = __int_as_float(e1.y);
        const float* zr0 = Zin + (size_t)e0.x * NCLASS;
        const float* zr1 = Zin + (size_t)e1.x * NCLASS;
        z0a = fmaf(w0, __ldg(zr0 + lane), z0a);
        z0b = fmaf(w1, __ldg(zr1 + lane), z0b);
        if (lane < 8) {
            z1a = fmaf(w0, __ldg(zr0 + 32 + lane), z1a);
            z1b = fmaf(w1, __ldg(zr1 + 32 + lane), z1b);
        }
    }
    if (i < end) {
        int2 e0 = __ldg(&g_edges[i]);
        float w0 = __int_as_float(e0.y);
        const float* zr0 = Zin + (size_t)e0.x * NCLASS;
        z0a = fmaf(w0, __ldg(zr0 + lane), z0a);
        if (lane < 8) z1a = fmaf(w0, __ldg(zr0 + 32 + lane), z1a);
    }

    float z0 = z0a + z0b + __ldg(b1 + lane);
    float z1 = (lane < 8) ? (z1a + z1b + __ldg(b1 + 32 + lane)) : -INFINITY;

    float m = fmaxf(z0, z1);
#pragma unroll
    for (int off = 16; off > 0; off >>= 1)
        m = fmaxf(m, __shfl_xor_sync(0xffffffffu, m, off));

    float es = expf(z0 - m) + ((lane < 8) ? expf(z1 - m) : 0.f);
#pragma unroll
    for (int off = 16; off > 0; off >>= 1)
        es += __shfl_xor_sync(0xffffffffu, es, off);

    float lse = logf(es);
    float* orow = out + (size_t)node * NCLASS;
    orow[lane] = z0 - m - lse;
    if (lane < 8) orow[32 + lane] = z1 - m - lse;
}

// ---------------------------------------------------------------------------
extern "C" void kernel_launch(void* const* d_in, const int* in_sizes, int n_in,
                              void* d_out, int out_size)
{
    const float* x    = (const float*)d_in[0];
    const int*   esrc = (const int*)  d_in[1];
    const int*   edst = (const int*)  d_in[2];
    const float* ew   = (const float*)d_in[3];
    const float* W0   = (const float*)d_in[4];
    const float* b0   = (const float*)d_in[5];
    const float* W1   = (const float*)d_in[6];
    const float* b1   = (const float*)d_in[7];
    float* out = (float*)d_out;

    int M = in_sizes[0] / NFEAT;   // 100000
    int E = in_sizes[1];           // 3200000

    float *H0p, *H1, *Z2p;
    int* cnt;
    cudaGetSymbolAddress((void**)&H0p, g_H0p);
    cudaGetSymbolAddress((void**)&H1,  g_H1);
    cudaGetSymbolAddress((void**)&Z2p, g_Z2p);
    cudaGetSymbolAddress((void**)&cnt, g_cnt);

    // CSR build
    cudaMemsetAsync(cnt, 0, (size_t)M * sizeof(int), 0);
    hist_kernel<<<(E + 255) / 256, 256>>>(edst, E);
    scan_kernel<<<1, 1024>>>(M);
    scatter_kernel<<<(E + 255) / 256, 256>>>(esrc, edst, ew, E);

    // Layer 1 dense projection
    gemm1_kernel<<<(M + 127) / 128, 256>>>(x, W0, H0p, M);

    // SPMM1 + bias + l2norm + relu (warp/node)
    {
        long long threads = (long long)M * 32;
        spmm1norm_kernel<<<(int)((threads + 255) / 256), 256>>>(H0p, b0, H1, M);
    }

    // Layer 2 dense projection
    gemm2_kernel<<<(M + 127) / 128, 256>>>(H1, W1, Z2p, M);

    // SPMM2 + bias + log_softmax (warp/node)
    {
        long long threads = (long long)M * 32;
        spmm2lsm_kernel<<<(int)((threads + 255) / 256), 256>>>(Z2p, b1, out, M);
    }
}

// round 3
// speedup vs baseline: 1.1908x; 1.0085x over previous
#include <cuda_runtime.h>
#include <cuda_fp16.h>
#include <math.h>

#define NFEAT  256
#define NHID   128
#define NCLASS 40
#define MAXN   100000
#define MAXE   3200000

struct alignas(8) half4 { __half2 a, b; };

// Scratch (allocation-free: __device__ globals).
__device__ __align__(256) __half g_H0p[MAXN * NHID];   // x @ W0 (fp16)
__device__ __align__(256) float  g_H1 [MAXN * NHID];   // normalized relu hidden (fp32)
__device__ __align__(256) __half g_Z2p[MAXN * NCLASS]; // H1 @ W1 (fp16)
__device__ __align__(256) int    g_cnt[MAXN];          // per-dst degree histogram
__device__ __align__(256) int    g_rowstart[MAXN + 1]; // CSR row pointers
__device__ __align__(256) int    g_cursor[MAXN];       // scatter cursors
__device__ __align__(256) int2   g_edges[MAXE];        // CSR payload: {src, w bits}

// ---------------------------------------------------------------------------
// CSR build step 1: histogram of destination nodes.
// ---------------------------------------------------------------------------
__global__ __launch_bounds__(256) void hist_kernel(
    const int* __restrict__ dst, int E)
{
    int e = blockIdx.x * blockDim.x + threadIdx.x;
    if (e < E) atomicAdd(&g_cnt[__ldg(dst + e)], 1);
}

// ---------------------------------------------------------------------------
// CSR build step 2: exclusive prefix sum over N counts. Single block, 1024 thr.
// ---------------------------------------------------------------------------
__global__ __launch_bounds__(1024) void scan_kernel(int N)
{
    __shared__ int s[1024];
    int t = threadIdx.x;
    int chunk = (N + 1023) / 1024;
    int beg = t * chunk;
    int end = min(beg + chunk, N);

    int sum = 0;
    for (int i = beg; i < end; i++) sum += g_cnt[i];
    s[t] = sum;
    __syncthreads();

#pragma unroll
    for (int off = 1; off < 1024; off <<= 1) {
        int v = (t >= off) ? s[t - off] : 0;
        __syncthreads();
        s[t] += v;
        __syncthreads();
    }

    int base = s[t] - sum;   // exclusive prefix
    for (int i = beg; i < end; i++) {
        g_rowstart[i] = base;
        g_cursor[i]   = base;
        base += g_cnt[i];
    }
    if (t == 1023) g_rowstart[N] = s[1023];
}

// ---------------------------------------------------------------------------
// CSR build step 3: scatter (src, w) into per-dst segments.
// ---------------------------------------------------------------------------
__global__ __launch_bounds__(256) void scatter_kernel(
    const int* __restrict__ src, const int* __restrict__ dst,
    const float* __restrict__ w, int E)
{
    int e = blockIdx.x * blockDim.x + threadIdx.x;
    if (e >= E) return;
    int d = __ldg(dst + e);
    int pos = atomicAdd(&g_cursor[d], 1);
    g_edges[pos] = make_int2(__ldg(src + e), __float_as_int(__ldg(w + e)));
}

// ---------------------------------------------------------------------------
// GEMM1: C[M,128] = A[M,256] @ B[256,128]. 128x128 tile, BK=8, 8x8/thread.
// Epilogue converts to fp16.
// ---------------------------------------------------------------------------
__global__ __launch_bounds__(256) void gemm1_kernel(
    const float* __restrict__ A, const float* __restrict__ B,
    __half* __restrict__ C, int M)
{
    __shared__ float As[8][128];
    __shared__ float Bs[8][128];

    int t = threadIdx.x;
    int blockRow = blockIdx.x * 128;

    int tx = t & 15;
    int ty = t >> 4;

    int aRow = t >> 1;
    int aCol = (t & 1) * 4;
    int bRow = t >> 5;
    int bCol = (t & 31) * 4;

    float acc[8][8];
#pragma unroll
    for (int i = 0; i < 8; i++)
#pragma unroll
        for (int j = 0; j < 8; j++) acc[i][j] = 0.f;

    for (int k0 = 0; k0 < NFEAT; k0 += 8) {
        int gr = blockRow + aRow;
        float4 av = make_float4(0.f, 0.f, 0.f, 0.f);
        if (gr < M) av = *(const float4*)(A + (size_t)gr * NFEAT + k0 + aCol);
        As[aCol + 0][aRow] = av.x;
        As[aCol + 1][aRow] = av.y;
        As[aCol + 2][aRow] = av.z;
        As[aCol + 3][aRow] = av.w;

        float4 bv = *(const float4*)(B + (size_t)(k0 + bRow) * NHID + bCol);
        *(float4*)&Bs[bRow][bCol] = bv;

        __syncthreads();

#pragma unroll
        for (int k = 0; k < 8; k++) {
            float4 a0 = *(float4*)&As[k][ty * 8];
            float4 a1 = *(float4*)&As[k][ty * 8 + 4];
            float4 b0 = *(float4*)&Bs[k][tx * 8];
            float4 b1 = *(float4*)&Bs[k][tx * 8 + 4];
            float ar[8] = {a0.x, a0.y, a0.z, a0.w, a1.x, a1.y, a1.z, a1.w};
            float br[8] = {b0.x, b0.y, b0.z, b0.w, b1.x, b1.y, b1.z, b1.w};
#pragma unroll
            for (int i = 0; i < 8; i++)
#pragma unroll
                for (int j = 0; j < 8; j++)
                    acc[i][j] = fmaf(ar[i], br[j], acc[i][j]);
        }
        __syncthreads();
    }

#pragma unroll
    for (int i = 0; i < 8; i++) {
        int gr = blockRow + ty * 8 + i;
        if (gr < M) {
            half4 h0, h1;
            h0.a = __floats2half2_rn(acc[i][0], acc[i][1]);
            h0.b = __floats2half2_rn(acc[i][2], acc[i][3]);
            h1.a = __floats2half2_rn(acc[i][4], acc[i][5]);
            h1.b = __floats2half2_rn(acc[i][6], acc[i][7]);
            *(half4*)(C + (size_t)gr * NHID + tx * 8)     = h0;
            *(half4*)(C + (size_t)gr * NHID + tx * 8 + 4) = h1;
        }
    }
}

// ---------------------------------------------------------------------------
// Fused SPMM1 + bias + L2 normalize + ReLU. Warp per dst node, CSR gather of
// fp16 rows, fp32 register accumulation (no atomics).
// ---------------------------------------------------------------------------
__global__ __launch_bounds__(256) void spmm1norm_kernel(
    const __half* __restrict__ Hin, const float* __restrict__ b0,
    float* __restrict__ Hout, int M)
{
    int gid = blockIdx.x * blockDim.x + threadIdx.x;
    int node = gid >> 5;
    if (node >= M) return;
    int lane = gid & 31;

    int beg = __ldg(&g_rowstart[node]);
    int end = __ldg(&g_rowstart[node + 1]);

    float4 a0 = make_float4(0.f, 0.f, 0.f, 0.f);
    float4 a1 = make_float4(0.f, 0.f, 0.f, 0.f);

    int i = beg;
    for (; i + 1 < end; i += 2) {
        int2 e0 = __ldg(&g_edges[i]);
        int2 e1 = __ldg(&g_edges[i + 1]);
        half4 v0 = *(const half4*)(Hin + (size_t)e0.x * NHID + lane * 4);
        half4 v1 = *(const half4*)(Hin + (size_t)e1.x * NHID + lane * 4);
        float w0 = __int_as_float(e0.y);
        float w1 = __int_as_float(e1.y);
        float2 f0a = __half22float2(v0.a), f0b = __half22float2(v0.b);
        float2 f1a = __half22float2(v1.a), f1b = __half22float2(v1.b);
        a0.x = fmaf(w0, f0a.x, a0.x); a0.y = fmaf(w0, f0a.y, a0.y);
        a0.z = fmaf(w0, f0b.x, a0.z); a0.w = fmaf(w0, f0b.y, a0.w);
        a1.x = fmaf(w1, f1a.x, a1.x); a1.y = fmaf(w1, f1a.y, a1.y);
        a1.z = fmaf(w1, f1b.x, a1.z); a1.w = fmaf(w1, f1b.y, a1.w);
    }
    if (i < end) {
        int2 e0 = __ldg(&g_edges[i]);
        half4 v0 = *(const half4*)(Hin + (size_t)e0.x * NHID + lane * 4);
        float w0 = __int_as_float(e0.y);
        float2 f0a = __half22float2(v0.a), f0b = __half22float2(v0.b);
        a0.x = fmaf(w0, f0a.x, a0.x); a0.y = fmaf(w0, f0a.y, a0.y);
        a0.z = fmaf(w0, f0b.x, a0.z); a0.w = fmaf(w0, f0b.y, a0.w);
    }

    float4 v;
    float4 b = *(const float4*)(b0 + lane * 4);
    v.x = a0.x + a1.x + b.x;
    v.y = a0.y + a1.y + b.y;
    v.z = a0.z + a1.z + b.z;
    v.w = a0.w + a1.w + b.w;

    float ss = v.x * v.x + v.y * v.y + v.z * v.z + v.w * v.w;
#pragma unroll
    for (int off = 16; off > 0; off >>= 1)
        ss += __shfl_xor_sync(0xffffffffu, ss, off);

    float scale = 1.0f / fmaxf(sqrtf(ss), 1e-12f);

    v.x = fmaxf(v.x * scale, 0.f);
    v.y = fmaxf(v.y * scale, 0.f);
    v.z = fmaxf(v.z * scale, 0.f);
    v.w = fmaxf(v.w * scale, 0.f);
    *(float4*)(Hout + (size_t)node * NHID + lane * 4) = v;
}

// ---------------------------------------------------------------------------
// GEMM2: Z[M,40] = H[M,128] @ W[128,40]. Vectorized LDS.128 both operands.
// Epilogue converts to fp16.
// ---------------------------------------------------------------------------
__global__ __launch_bounds__(256) void gemm2_kernel(
    const float* __restrict__ H, const float* __restrict__ W,
    __half* __restrict__ Z, int M)
{
    __shared__ float hs[128][68];
    __shared__ float wsT[40][68];

    int t = threadIdx.x;
    int node0 = blockIdx.x * 128;
    int ng = t & 31, cg = t >> 5;

    float acc[4][5];
#pragma unroll
    for (int i = 0; i < 4; i++)
#pragma unroll
        for (int j = 0; j < 5; j++) acc[i][j] = 0.f;

#pragma unroll
    for (int h = 0; h < 2; h++) {
        int k0 = h * 64;
        for (int i = t; i < 64 * NCLASS; i += 256) {
            int k = i & 63, c = i >> 6;
            wsT[c][k] = W[(size_t)(k0 + k) * NCLASS + c];
        }

        for (int i = t * 4; i < 128 * 64; i += 256 * 4) {
            int node = i >> 6, k = i & 63;
            int gn = node0 + node;
            float4 v = make_float4(0.f, 0.f, 0.f, 0.f);
            if (gn < M) v = *(const float4*)(H + (size_t)gn * NHID + k0 + k);
            hs[node][k + 0] = v.x;
            hs[node][k + 1] = v.y;
            hs[node][k + 2] = v.z;
            hs[node][k + 3] = v.w;
        }
        __syncthreads();

#pragma unroll 4
        for (int k = 0; k < 64; k += 4) {
            float4 b[5];
#pragma unroll
            for (int j = 0; j < 5; j++) b[j] = *(float4*)&wsT[cg * 5 + j][k];
#pragma unroll
            for (int i = 0; i < 4; i++) {
                float4 a = *(float4*)&hs[ng + 32 * i][k];
#pragma unroll
                for (int j = 0; j < 5; j++) {
                    acc[i][j] = fmaf(a.x, b[j].x, acc[i][j]);
                    acc[i][j] = fmaf(a.y, b[j].y, acc[i][j]);
                    acc[i][j] = fmaf(a.z, b[j].z, acc[i][j]);
                    acc[i][j] = fmaf(a.w, b[j].w, acc[i][j]);
                }
            }
        }
        __syncthreads();
    }

#pragma unroll
    for (int i = 0; i < 4; i++) {
        int gn = node0 + ng + 32 * i;
        if (gn < M)
#pragma unroll
            for (int j = 0; j < 5; j++)
                Z[(size_t)gn * NCLASS + cg * 5 + j] = __float2half_rn(acc[i][j]);
    }
}

// ---------------------------------------------------------------------------
// Fused SPMM2 + bias + log_softmax. Warp per dst node, fp16 CSR gather.
// Lane covers class {lane} and (lane<8) {lane+32}.
// ---------------------------------------------------------------------------
__global__ __launch_bounds__(256) void spmm2lsm_kernel(
    const __half* __restrict__ Zin, const float* __restrict__ b1,
    float* __restrict__ out, int M)
{
    int gid = blockIdx.x * blockDim.x + threadIdx.x;
    int node = gid >> 5;
    if (node >= M) return;
    int lane = gid & 31;

    int beg = __ldg(&g_rowstart[node]);
    int end = __ldg(&g_rowstart[node + 1]);

    float z0a = 0.f, z0b = 0.f, z1a = 0.f, z1b = 0.f;

    int i = beg;
    for (; i + 1 < end; i += 2) {
        int2 e0 = __ldg(&g_edges[i]);
        int2 e1 = __ldg(&g_edges[i + 1]);
        float w0 = __int_as_float(e0.y);
        float w1 = __int_as_float(e1.y);
        const __half* zr0 = Zin + (size_t)e0.x * NCLASS;
        const __half* zr1 = Zin + (size_t)e1.x * NCLASS;
        z0a = fmaf(w0, __half2float(__ldg(zr0 + lane)), z0a);
        z0b = fmaf(w1, __half2float(__ldg(zr1 + lane)), z0b);
        if (lane < 8) {
            z1a = fmaf(w0, __half2float(__ldg(zr0 + 32 + lane)), z1a);
            z1b = fmaf(w1, __half2float(__ldg(zr1 + 32 + lane)), z1b);
        }
    }
    if (i < end) {
        int2 e0 = __ldg(&g_edges[i]);
        float w0 = __int_as_float(e0.y);
        const __half* zr0 = Zin + (size_t)e0.x * NCLASS;
        z0a = fmaf(w0, __half2float(__ldg(zr0 + lane)), z0a);
        if (lane < 8) z1a = fmaf(w0, __half2float(__ldg(zr0 + 32 + lane)), z1a);
    }

    float z0 = z0a + z0b + __ldg(b1 + lane);
    float z1 = (lane < 8) ? (z1a + z1b + __ldg(b1 + 32 + lane)) : -INFINITY;

    float m = fmaxf(z0, z1);
#pragma unroll
    for (int off = 16; off > 0; off >>= 1)
        m = fmaxf(m, __shfl_xor_sync(0xffffffffu, m, off));

    float es = expf(z0 - m) + ((lane < 8) ? expf(z1 - m) : 0.f);
#pragma unroll
    for (int off = 16; off > 0; off >>= 1)
        es += __shfl_xor_sync(0xffffffffu, es, off);

    float lse = logf(es);
    float* orow = out + (size_t)node * NCLASS;
    orow[lane] = z0 - m - lse;
    if (lane < 8) orow[32 + lane] = z1 - m - lse;
}

// ---------------------------------------------------------------------------
extern "C" void kernel_launch(void* const* d_in, const int* in_sizes, int n_in,
                              void* d_out, int out_size)
{
    const float* x    = (const float*)d_in[0];
    const int*   esrc = (const int*)  d_in[1];
    const int*   edst = (const int*)  d_in[2];
    const float* ew   = (const float*)d_in[3];
    const float* W0   = (const float*)d_in[4];
    const float* b0   = (const float*)d_in[5];
    const float* W1   = (const float*)d_in[6];
    const float* b1   = (const float*)d_in[7];
    float* out = (float*)d_out;

    int M = in_sizes[0] / NFEAT;   // 100000
    int E = in_sizes[1];           // 3200000

    __half *H0p, *Z2p;
    float *H1;
    int* cnt;
    cudaGetSymbolAddress((void**)&H0p, g_H0p);
    cudaGetSymbolAddress((void**)&H1,  g_H1);
    cudaGetSymbolAddress((void**)&Z2p, g_Z2p);
    cudaGetSymbolAddress((void**)&cnt, g_cnt);

    // CSR build
    cudaMemsetAsync(cnt, 0, (size_t)M * sizeof(int), 0);
    hist_kernel<<<(E + 255) / 256, 256>>>(edst, E);
    scan_kernel<<<1, 1024>>>(M);
    scatter_kernel<<<(E + 255) / 256, 256>>>(esrc, edst, ew, E);

    // Layer 1 dense projection (fp32 -> fp16 out)
    gemm1_kernel<<<(M + 127) / 128, 256>>>(x, W0, H0p, M);

    // SPMM1 + bias + l2norm + relu (warp/node)
    {
        long long threads = (long long)M * 32;
        spmm1norm_kernel<<<(int)((threads + 255) / 256), 256>>>(H0p, b0, H1, M);
    }

    // Layer 2 dense projection (fp32 -> fp16 out)
    gemm2_kernel<<<(M + 127) / 128, 256>>>(H1, W1, Z2p, M);

    // SPMM2 + bias + log_softmax (warp/node)
    {
        long long threads = (long long)M * 32;
        spmm2lsm_kernel<<<(int)((threads + 255) / 256), 256>>>(Z2p, b1, out, M);
    }
}

// round 5
// speedup vs baseline: 1.3107x; 1.1007x over previous
#include <cuda_runtime.h>
#include <cuda_fp16.h>
#include <cuda_bf16.h>
#include <mma.h>
#include <math.h>
#include <stdint.h>

using namespace nvcuda;

#define NFEAT  256
#define NHID   128
#define NCLASS 40
#define MAXN   100000
#define MAXE   3200000

struct alignas(8) half4 { __half2 a, b; };

// Scratch (allocation-free: __device__ globals).
__device__ __align__(256) __half g_H0p[MAXN * NHID];   // x @ W0 (fp16)
__device__ __align__(256) float  g_H1 [MAXN * NHID];   // normalized relu hidden (fp32)
__device__ __align__(256) __half g_Z2p[MAXN * NCLASS]; // H1 @ W1 (fp16)
__device__ __align__(256) int    g_cnt[MAXN];          // per-dst degree histogram
__device__ __align__(256) int    g_rowstart[MAXN + 1]; // CSR row pointers
__device__ __align__(256) int    g_cursor[MAXN];       // scatter cursors
__device__ __align__(256) int2   g_edges[MAXE];        // CSR payload: {src, w bits}

// ---------------------------------------------------------------------------
// GEMM1 via WMMA split-bf16: C[M,128] = A[M,256] @ W0[256,128].
// A, B decomposed as bf16 hi + lo; acc += Ah*Bh + Ah*Bl + Al*Bh (fp32 accum).
// CTA tile 128x128, 8 warps (4 along M x 2 along N), warp tile 32x64, BK=64.
// ---------------------------------------------------------------------------
#define G1_LDA 72    // A smem row stride (elements)
#define G1_LDB 136   // B smem row stride (elements)
// smem bytes: A hi/lo 2*128*72*2 = 36864; B hi/lo 2*64*136*2 = 34816 -> 71680
#define G1_SMEM 71680

__global__ __launch_bounds__(256)
void gemm1_wmma_kernel(const float* __restrict__ A, const float* __restrict__ B,
                       __half* __restrict__ C, int M)
{
    extern __shared__ __align__(16) char sm[];
    __nv_bfloat16* As_hi = (__nv_bfloat16*)sm;                 // [128][72]
    __nv_bfloat16* As_lo = As_hi + 128 * G1_LDA;
    __nv_bfloat16* Bs_hi = As_lo + 128 * G1_LDA;               // [64][136]
    __nv_bfloat16* Bs_lo = Bs_hi + 64 * G1_LDB;

    int tid  = threadIdx.x;
    int warp = tid >> 5;
    int lane = tid & 31;
    int wm = warp & 3;        // 0..3 -> M offset 32*wm
    int wn = warp >> 2;       // 0..1 -> N offset 64*wn
    int blockRow = blockIdx.x * 128;

    wmma::fragment<wmma::accumulator, 16, 16, 16, float> acc[2][4];
#pragma unroll
    for (int i = 0; i < 2; i++)
#pragma unroll
        for (int j = 0; j < 4; j++) wmma::fill_fragment(acc[i][j], 0.0f);

    for (int k0 = 0; k0 < NFEAT; k0 += 64) {
        // Load A chunk: 128 rows x 64 cols. 16 float4 per row.
        for (int q = tid; q < 128 * 16; q += 256) {
            int r  = q >> 4;
            int c4 = (q & 15) * 4;
            int gr = blockRow + r;
            float4 v = make_float4(0.f, 0.f, 0.f, 0.f);
            if (gr < M) v = *(const float4*)(A + (size_t)gr * NFEAT + k0 + c4);
            float vv[4] = {v.x, v.y, v.z, v.w};
            __nv_bfloat16* ph = As_hi + r * G1_LDA + c4;
            __nv_bfloat16* pl = As_lo + r * G1_LDA + c4;
#pragma unroll
            for (int j = 0; j < 4; j++) {
                __nv_bfloat16 hi = __float2bfloat16_rn(vv[j]);
                ph[j] = hi;
                pl[j] = __float2bfloat16_rn(vv[j] - __bfloat162float(hi));
            }
        }
        // Load B chunk: 64 rows x 128 cols. 32 float4 per row.
        for (int q = tid; q < 64 * 32; q += 256) {
            int r  = q >> 5;
            int c4 = (q & 31) * 4;
            float4 v = *(const float4*)(B + (size_t)(k0 + r) * NHID + c4);
            float vv[4] = {v.x, v.y, v.z, v.w};
            __nv_bfloat16* ph = Bs_hi + r * G1_LDB + c4;
            __nv_bfloat16* pl = Bs_lo + r * G1_LDB + c4;
#pragma unroll
            for (int j = 0; j < 4; j++) {
                __nv_bfloat16 hi = __float2bfloat16_rn(vv[j]);
                ph[j] = hi;
                pl[j] = __float2bfloat16_rn(vv[j] - __bfloat162float(hi));
            }
        }
        __syncthreads();

#pragma unroll
        for (int kk = 0; kk < 64; kk += 16) {
            wmma::fragment<wmma::matrix_a, 16, 16, 16, __nv_bfloat16, wmma::row_major> a_hi[2], a_lo[2];
            wmma::fragment<wmma::matrix_b, 16, 16, 16, __nv_bfloat16, wmma::row_major> b_hi[4], b_lo[4];
#pragma unroll
            for (int i = 0; i < 2; i++) {
                const __nv_bfloat16* pa = As_hi + (wm * 32 + i * 16) * G1_LDA + kk;
                wmma::load_matrix_sync(a_hi[i], pa, G1_LDA);
                wmma::load_matrix_sync(a_lo[i], pa + 128 * G1_LDA, G1_LDA);
            }
#pragma unroll
            for (int j = 0; j < 4; j++) {
                const __nv_bfloat16* pb = Bs_hi + kk * G1_LDB + wn * 64 + j * 16;
                wmma::load_matrix_sync(b_hi[j], pb, G1_LDB);
                wmma::load_matrix_sync(b_lo[j], pb + 64 * G1_LDB, G1_LDB);
            }
#pragma unroll
            for (int i = 0; i < 2; i++)
#pragma unroll
                for (int j = 0; j < 4; j++) {
                    wmma::mma_sync(acc[i][j], a_hi[i], b_hi[j], acc[i][j]);
                    wmma::mma_sync(acc[i][j], a_hi[i], b_lo[j], acc[i][j]);
                    wmma::mma_sync(acc[i][j], a_lo[i], b_hi[j], acc[i][j]);
                }
        }
        __syncthreads();
    }

    // Epilogue: stage fp32 warp tile (32x64) in smem, convert to fp16, STG.
    float* st = (float*)sm + warp * (32 * 64);
#pragma unroll
    for (int i = 0; i < 2; i++)
#pragma unroll
        for (int j = 0; j < 4; j++)
            wmma::store_matrix_sync(st + (i * 16) * 64 + j * 16, acc[i][j], 64,
                                    wmma::mem_row_major);
    __syncwarp();

    int row = blockRow + wm * 32 + lane;
    if (row < M) {
        __half* dst = C + (size_t)row * NHID + wn * 64;
        const float* srow = st + lane * 64;
#pragma unroll
        for (int c = 0; c < 64; c += 8) {
            float4 f0 = *(const float4*)(srow + c);
            float4 f1 = *(const float4*)(srow + c + 4);
            uint4 o;
            __half2 h;
            h = __floats2half2_rn(f0.x, f0.y); o.x = *(uint32_t*)&h;
            h = __floats2half2_rn(f0.z, f0.w); o.y = *(uint32_t*)&h;
            h = __floats2half2_rn(f1.x, f1.y); o.z = *(uint32_t*)&h;
            h = __floats2half2_rn(f1.z, f1.w); o.w = *(uint32_t*)&h;
            *(uint4*)(dst + c) = o;
        }
    }
}

// ---------------------------------------------------------------------------
// CSR build step 1: histogram of destination nodes.
// ---------------------------------------------------------------------------
__global__ __launch_bounds__(256) void hist_kernel(
    const int* __restrict__ dst, int E)
{
    int e = blockIdx.x * blockDim.x + threadIdx.x;
    if (e < E) atomicAdd(&g_cnt[__ldg(dst + e)], 1);
}

// ---------------------------------------------------------------------------
// CSR build step 2: exclusive prefix sum over N counts. Single block, 1024 thr.
// ---------------------------------------------------------------------------
__global__ __launch_bounds__(1024) void scan_kernel(int N)
{
    __shared__ int s[1024];
    int t = threadIdx.x;
    int chunk = (N + 1023) / 1024;
    int beg = t * chunk;
    int end = min(beg + chunk, N);

    int sum = 0;
    for (int i = beg; i < end; i++) sum += g_cnt[i];
    s[t] = sum;
    __syncthreads();

#pragma unroll
    for (int off = 1; off < 1024; off <<= 1) {
        int v = (t >= off) ? s[t - off] : 0;
        __syncthreads();
        s[t] += v;
        __syncthreads();
    }

    int base = s[t] - sum;   // exclusive prefix
    for (int i = beg; i < end; i++) {
        g_rowstart[i] = base;
        g_cursor[i]   = base;
        base += g_cnt[i];
    }
    if (t == 1023) g_rowstart[N] = s[1023];
}

// ---------------------------------------------------------------------------
// CSR build step 3: scatter (src, w) into per-dst segments.
// ---------------------------------------------------------------------------
__global__ __launch_bounds__(256) void scatter_kernel(
    const int* __restrict__ src, const int* __restrict__ dst,
    const float* __restrict__ w, int E)
{
    int e = blockIdx.x * blockDim.x + threadIdx.x;
    if (e >= E) return;
    int d = __ldg(dst + e);
    int pos = atomicAdd(&g_cursor[d], 1);
    g_edges[pos] = make_int2(__ldg(src + e), __float_as_int(__ldg(w + e)));
}

// ---------------------------------------------------------------------------
// Fused SPMM1 + bias + L2 normalize + ReLU. Warp per dst node, CSR gather of
// fp16 rows, fp32 register accumulation (no atomics).
// ---------------------------------------------------------------------------
__global__ __launch_bounds__(256) void spmm1norm_kernel(
    const __half* __restrict__ Hin, const float* __restrict__ b0,
    float* __restrict__ Hout, int M)
{
    int gid = blockIdx.x * blockDim.x + threadIdx.x;
    int node = gid >> 5;
    if (node >= M) return;
    int lane = gid & 31;

    int beg = __ldg(&g_rowstart[node]);
    int end = __ldg(&g_rowstart[node + 1]);

    float4 a0 = make_float4(0.f, 0.f, 0.f, 0.f);
    float4 a1 = make_float4(0.f, 0.f, 0.f, 0.f);

    int i = beg;
    for (; i + 1 < end; i += 2) {
        int2 e0 = __ldg(&g_edges[i]);
        int2 e1 = __ldg(&g_edges[i + 1]);
        half4 v0 = *(const half4*)(Hin + (size_t)e0.x * NHID + lane * 4);
        half4 v1 = *(const half4*)(Hin + (size_t)e1.x * NHID + lane * 4);
        float w0 = __int_as_float(e0.y);
        float w1 = __int_as_float(e1.y);
        float2 f0a = __half22float2(v0.a), f0b = __half22float2(v0.b);
        float2 f1a = __half22float2(v1.a), f1b = __half22float2(v1.b);
        a0.x = fmaf(w0, f0a.x, a0.x); a0.y = fmaf(w0, f0a.y, a0.y);
        a0.z = fmaf(w0, f0b.x, a0.z); a0.w = fmaf(w0, f0b.y, a0.w);
        a1.x = fmaf(w1, f1a.x, a1.x); a1.y = fmaf(w1, f1a.y, a1.y);
        a1.z = fmaf(w1, f1b.x, a1.z); a1.w = fmaf(w1, f1b.y, a1.w);
    }
    if (i < end) {
        int2 e0 = __ldg(&g_edges[i]);
        half4 v0 = *(const half4*)(Hin + (size_t)e0.x * NHID + lane * 4);
        float w0 = __int_as_float(e0.y);
        float2 f0a = __half22float2(v0.a), f0b = __half22float2(v0.b);
        a0.x = fmaf(w0, f0a.x, a0.x); a0.y = fmaf(w0, f0a.y, a0.y);
        a0.z = fmaf(w0, f0b.x, a0.z); a0.w = fmaf(w0, f0b.y, a0.w);
    }

    float4 v;
    float4 b = *(const float4*)(b0 + lane * 4);
    v.x = a0.x + a1.x + b.x;
    v.y = a0.y + a1.y + b.y;
    v.z = a0.z + a1.z + b.z;
    v.w = a0.w + a1.w + b.w;

    float ss = v.x * v.x + v.y * v.y + v.z * v.z + v.w * v.w;
#pragma unroll
    for (int off = 16; off > 0; off >>= 1)
        ss += __shfl_xor_sync(0xffffffffu, ss, off);

    float scale = 1.0f / fmaxf(sqrtf(ss), 1e-12f);

    v.x = fmaxf(v.x * scale, 0.f);
    v.y = fmaxf(v.y * scale, 0.f);
    v.z = fmaxf(v.z * scale, 0.f);
    v.w = fmaxf(v.w * scale, 0.f);
    *(float4*)(Hout + (size_t)node * NHID + lane * 4) = v;
}

// ---------------------------------------------------------------------------
// GEMM2: Z[M,40] = H[M,128] @ W[128,40]. Vectorized LDS.128 both operands.
// Epilogue converts to fp16.
// ---------------------------------------------------------------------------
__global__ __launch_bounds__(256) void gemm2_kernel(
    const float* __restrict__ H, const float* __restrict__ W,
    __half* __restrict__ Z, int M)
{
    __shared__ float hs[128][68];
    __shared__ float wsT[40][68];

    int t = threadIdx.x;
    int node0 = blockIdx.x * 128;
    int ng = t & 31, cg = t >> 5;

    float acc[4][5];
#pragma unroll
    for (int i = 0; i < 4; i++)
#pragma unroll
        for (int j = 0; j < 5; j++) acc[i][j] = 0.f;

#pragma unroll
    for (int h = 0; h < 2; h++) {
        int k0 = h * 64;
        for (int i = t; i < 64 * NCLASS; i += 256) {
            int k = i & 63, c = i >> 6;
            wsT[c][k] = W[(size_t)(k0 + k) * NCLASS + c];
        }

        for (int i = t * 4; i < 128 * 64; i += 256 * 4) {
            int node = i >> 6, k = i & 63;
            int gn = node0 + node;
            float4 v = make_float4(0.f, 0.f, 0.f, 0.f);
            if (gn < M) v = *(const float4*)(H + (size_t)gn * NHID + k0 + k);
            hs[node][k + 0] = v.x;
            hs[node][k + 1] = v.y;
            hs[node][k + 2] = v.z;
            hs[node][k + 3] = v.w;
        }
        __syncthreads();

#pragma unroll 4
        for (int k = 0; k < 64; k += 4) {
            float4 b[5];
#pragma unroll
            for (int j = 0; j < 5; j++) b[j] = *(float4*)&wsT[cg * 5 + j][k];
#pragma unroll
            for (int i = 0; i < 4; i++) {
                float4 a = *(float4*)&hs[ng + 32 * i][k];
#pragma unroll
                for (int j = 0; j < 5; j++) {
                    acc[i][j] = fmaf(a.x, b[j].x, acc[i][j]);
                    acc[i][j] = fmaf(a.y, b[j].y, acc[i][j]);
                    acc[i][j] = fmaf(a.z, b[j].z, acc[i][j]);
                    acc[i][j] = fmaf(a.w, b[j].w, acc[i][j]);
                }
            }
        }
        __syncthreads();
    }

#pragma unroll
    for (int i = 0; i < 4; i++) {
        int gn = node0 + ng + 32 * i;
        if (gn < M)
#pragma unroll
            for (int j = 0; j < 5; j++)
                Z[(size_t)gn * NCLASS + cg * 5 + j] = __float2half_rn(acc[i][j]);
    }
}

// ---------------------------------------------------------------------------
// Fused SPMM2 + bias + log_softmax. Warp per dst node, fp16 CSR gather.
// ---------------------------------------------------------------------------
__global__ __launch_bounds__(256) void spmm2lsm_kernel(
    const __half* __restrict__ Zin, const float* __restrict__ b1,
    float* __restrict__ out, int M)
{
    int gid = blockIdx.x * blockDim.x + threadIdx.x;
    int node = gid >> 5;
    if (node >= M) return;
    int lane = gid & 31;

    int beg = __ldg(&g_rowstart[node]);
    int end = __ldg(&g_rowstart[node + 1]);

    float z0a = 0.f, z0b = 0.f, z1a = 0.f, z1b = 0.f;

    int i = beg;
    for (; i + 1 < end; i += 2) {
        int2 e0 = __ldg(&g_edges[i]);
        int2 e1 = __ldg(&g_edges[i + 1]);
        float w0 = __int_as_float(e0.y);
        float w1 = __int_as_float(e1.y);
        const __half* zr0 = Zin + (size_t)e0.x * NCLASS;
        const __half* zr1 = Zin + (size_t)e1.x * NCLASS;
        z0a = fmaf(w0, __half2float(__ldg(zr0 + lane)), z0a);
        z0b = fmaf(w1, __half2float(__ldg(zr1 + lane)), z0b);
        if (lane < 8) {
            z1a = fmaf(w0, __half2float(__ldg(zr0 + 32 + lane)), z1a);
            z1b = fmaf(w1, __half2float(__ldg(zr1 + 32 + lane)), z1b);
        }
    }
    if (i < end) {
        int2 e0 = __ldg(&g_edges[i]);
        float w0 = __int_as_float(e0.y);
        const __half* zr0 = Zin + (size_t)e0.x * NCLASS;
        z0a = fmaf(w0, __half2float(__ldg(zr0 + lane)), z0a);
        if (lane < 8) z1a = fmaf(w0, __half2float(__ldg(zr0 + 32 + lane)), z1a);
    }

    float z0 = z0a + z0b + __ldg(b1 + lane);
    float z1 = (lane < 8) ? (z1a + z1b + __ldg(b1 + 32 + lane)) : -INFINITY;

    float m = fmaxf(z0, z1);
#pragma unroll
    for (int off = 16; off > 0; off >>= 1)
        m = fmaxf(m, __shfl_xor_sync(0xffffffffu, m, off));

    float es = expf(z0 - m) + ((lane < 8) ? expf(z1 - m) : 0.f);
#pragma unroll
    for (int off = 16; off > 0; off >>= 1)
        es += __shfl_xor_sync(0xffffffffu, es, off);

    float lse = logf(es);
    float* orow = out + (size_t)node * NCLASS;
    orow[lane] = z0 - m - lse;
    if (lane < 8) orow[32 + lane] = z1 - m - lse;
}

// ---------------------------------------------------------------------------
extern "C" void kernel_launch(void* const* d_in, const int* in_sizes, int n_in,
                              void* d_out, int out_size)
{
    const float* x    = (const float*)d_in[0];
    const int*   esrc = (const int*)  d_in[1];
    const int*   edst = (const int*)  d_in[2];
    const float* ew   = (const float*)d_in[3];
    const float* W0   = (const float*)d_in[4];
    const float* b0   = (const float*)d_in[5];
    const float* W1   = (const float*)d_in[6];
    const float* b1   = (const float*)d_in[7];
    float* out = (float*)d_out;

    int M = in_sizes[0] / NFEAT;   // 100000
    int E = in_sizes[1];           // 3200000

    __half *H0p, *Z2p;
    float *H1;
    int* cnt;
    cudaGetSymbolAddress((void**)&H0p, g_H0p);
    cudaGetSymbolAddress((void**)&H1,  g_H1);
    cudaGetSymbolAddress((void**)&Z2p, g_Z2p);
    cudaGetSymbolAddress((void**)&cnt, g_cnt);

    // CSR build
    cudaMemsetAsync(cnt, 0, (size_t)M * sizeof(int), 0);
    hist_kernel<<<(E + 255) / 256, 256>>>(edst, E);
    scan_kernel<<<1, 1024>>>(M);
    scatter_kernel<<<(E + 255) / 256, 256>>>(esrc, edst, ew, E);

    // Layer 1 dense projection via WMMA split-bf16 (fp16 out)
    cudaFuncSetAttribute(gemm1_wmma_kernel,
                         cudaFuncAttributeMaxDynamicSharedMemorySize, G1_SMEM);
    gemm1_wmma_kernel<<<(M + 127) / 128, 256, G1_SMEM>>>(x, W0, H0p, M);

    // SPMM1 + bias + l2norm + relu (warp/node)
    {
        long long threads = (long long)M * 32;
        spmm1norm_kernel<<<(int)((threads + 255) / 256), 256>>>(H0p, b0, H1, M);
    }

    // Layer 2 dense projection (fp32 -> fp16 out)
    gemm2_kernel<<<(M + 127) / 128, 256>>>(H1, W1, Z2p, M);

    // SPMM2 + bias + log_softmax (warp/node)
    {
        long long threads = (long long)M * 32;
        spmm2lsm_kernel<<<(int)((threads + 255) / 256), 256>>>(Z2p, b1, out, M);
    }
}

// round 6
// speedup vs baseline: 1.3356x; 1.0190x over previous
#include <cuda_runtime.h>
#include <cuda_fp16.h>
#include <cuda_bf16.h>
#include <mma.h>
#include <math.h>
#include <stdint.h>

using namespace nvcuda;

#define NFEAT  256
#define NHID   128
#define NCLASS 40
#define MAXN   100000
#define MAXE   3200000

struct alignas(8) half4 { __half2 a, b; };

// Scratch (allocation-free: __device__ globals).
__device__ __align__(256) __half g_H0p[MAXN * NHID];   // x @ W0 (fp16)
__device__ __align__(256) float  g_H1 [MAXN * NHID];   // normalized relu hidden (fp32)
__device__ __align__(256) __half g_Z2p[MAXN * NCLASS]; // H1 @ W1 (fp16)
__device__ __align__(256) int    g_cnt[MAXN];          // per-dst degree histogram
__device__ __align__(256) int    g_rowstart[MAXN + 1]; // CSR row pointers
__device__ __align__(256) int    g_cursor[MAXN];       // scatter cursors
__device__ __align__(256) int2   g_edges[MAXE];        // CSR payload: {src, w bits}

// ---------------------------------------------------------------------------
// GEMM1 via WMMA split-bf16: C[M,128] = A[M,256] @ W0[256,128].
// acc += Ah*Bh + Ah*Bl + Al*Bh (fp32 accum). CTA tile 128x128, BK=32,
// 8 warps (4 M x 2 N), warp tile 32x64. 2 CTAs/SM + register prefetch.
// ---------------------------------------------------------------------------
#define G1_LDA 40    // A smem row stride (bf16 elements), 32 + 8 pad
#define G1_LDB 136   // B smem row stride (bf16 elements), 128 + 8 pad
// smem: Ahi 128*40*2=10240, Alo 10240, Bhi 32*136*2=8704, Blo 8704 -> 37888 B
#define G1_AHI 0
#define G1_ALO (128 * G1_LDA)
#define G1_BHI (2 * 128 * G1_LDA)
#define G1_BLO (2 * 128 * G1_LDA + 32 * G1_LDB)
#define G1_SMEM 37888

__global__ __launch_bounds__(256, 2)
void gemm1_wmma_kernel(const float* __restrict__ A, const float* __restrict__ B,
                       __half* __restrict__ C, int M)
{
    extern __shared__ __align__(16) char sm[];
    __nv_bfloat16* sb = (__nv_bfloat16*)sm;

    int tid  = threadIdx.x;
    int warp = tid >> 5;
    int lane = tid & 31;
    int wm = warp & 3;        // 0..3 -> M offset 32*wm
    int wn = warp >> 2;       // 0..1 -> N offset 64*wn
    int blockRow = blockIdx.x * 128;

    // Per-thread load coordinates (4 float4 each for A and B per chunk)
    int aRow[4], aC4[4], bRow[4], bC4[4];
    bool aOk[4];
#pragma unroll
    for (int i = 0; i < 4; i++) {
        int idx = tid + i * 256;
        aRow[i] = idx >> 3;  aC4[i] = (idx & 7) * 4;
        aOk[i]  = (blockRow + aRow[i]) < M;
        bRow[i] = idx >> 5;  bC4[i] = (idx & 31) * 4;
    }

    wmma::fragment<wmma::accumulator, 16, 16, 16, float> acc[2][4];
#pragma unroll
    for (int i = 0; i < 2; i++)
#pragma unroll
        for (int j = 0; j < 4; j++) wmma::fill_fragment(acc[i][j], 0.0f);

    float4 pa[4], pb[4];
    // Prefetch chunk 0
#pragma unroll
    for (int i = 0; i < 4; i++) {
        pa[i] = aOk[i] ? *(const float4*)(A + (size_t)(blockRow + aRow[i]) * NFEAT + aC4[i])
                       : make_float4(0.f, 0.f, 0.f, 0.f);
        pb[i] = *(const float4*)(B + (size_t)bRow[i] * NHID + bC4[i]);
    }

    for (int c = 0; c < 8; c++) {
        // Convert + store current chunk to smem
#pragma unroll
        for (int i = 0; i < 4; i++) {
            float vv[4] = {pa[i].x, pa[i].y, pa[i].z, pa[i].w};
            __nv_bfloat16* ph = sb + G1_AHI + aRow[i] * G1_LDA + aC4[i];
            __nv_bfloat16* pl = sb + G1_ALO + aRow[i] * G1_LDA + aC4[i];
#pragma unroll
            for (int j = 0; j < 4; j++) {
                __nv_bfloat16 hi = __float2bfloat16_rn(vv[j]);
                ph[j] = hi;
                pl[j] = __float2bfloat16_rn(vv[j] - __bfloat162float(hi));
            }
        }
#pragma unroll
        for (int i = 0; i < 4; i++) {
            float vv[4] = {pb[i].x, pb[i].y, pb[i].z, pb[i].w};
            __nv_bfloat16* ph = sb + G1_BHI + bRow[i] * G1_LDB + bC4[i];
            __nv_bfloat16* pl = sb + G1_BLO + bRow[i] * G1_LDB + bC4[i];
#pragma unroll
            for (int j = 0; j < 4; j++) {
                __nv_bfloat16 hi = __float2bfloat16_rn(vv[j]);
                ph[j] = hi;
                pl[j] = __float2bfloat16_rn(vv[j] - __bfloat162float(hi));
            }
        }
        __syncthreads();

        // Prefetch next chunk (overlaps with MMA phase)
        if (c < 7) {
            int k0 = (c + 1) * 32;
#pragma unroll
            for (int i = 0; i < 4; i++) {
                pa[i] = aOk[i] ? *(const float4*)(A + (size_t)(blockRow + aRow[i]) * NFEAT + k0 + aC4[i])
                               : make_float4(0.f, 0.f, 0.f, 0.f);
                pb[i] = *(const float4*)(B + (size_t)(k0 + bRow[i]) * NHID + bC4[i]);
            }
        }

        // MMA phase over BK=32 (2 kk-steps)
#pragma unroll
        for (int kk = 0; kk < 32; kk += 16) {
            wmma::fragment<wmma::matrix_a, 16, 16, 16, __nv_bfloat16, wmma::row_major> a_hi[2], a_lo[2];
#pragma unroll
            for (int i = 0; i < 2; i++) {
                const __nv_bfloat16* pa_ = sb + G1_AHI + (wm * 32 + i * 16) * G1_LDA + kk;
                wmma::load_matrix_sync(a_hi[i], pa_, G1_LDA);
                wmma::load_matrix_sync(a_lo[i], pa_ + (G1_ALO - G1_AHI), G1_LDA);
            }
#pragma unroll
            for (int j = 0; j < 4; j++) {
                wmma::fragment<wmma::matrix_b, 16, 16, 16, __nv_bfloat16, wmma::row_major> b_hi, b_lo;
                const __nv_bfloat16* pb_ = sb + G1_BHI + kk * G1_LDB + wn * 64 + j * 16;
                wmma::load_matrix_sync(b_hi, pb_, G1_LDB);
                wmma::load_matrix_sync(b_lo, pb_ + (G1_BLO - G1_BHI), G1_LDB);
#pragma unroll
                for (int i = 0; i < 2; i++) {
                    wmma::mma_sync(acc[i][j], a_hi[i], b_hi, acc[i][j]);
                    wmma::mma_sync(acc[i][j], a_hi[i], b_lo, acc[i][j]);
                    wmma::mma_sync(acc[i][j], a_lo[i], b_hi, acc[i][j]);
                }
            }
        }
        __syncthreads();
    }

    // Epilogue in two half-rounds (4 warps x 8KB fp32 staging fits 37.9KB smem)
    float* st = (float*)sm + wm * (32 * 64);
#pragma unroll
    for (int ph = 0; ph < 2; ph++) {
        if (wn == ph) {
#pragma unroll
            for (int i = 0; i < 2; i++)
#pragma unroll
                for (int j = 0; j < 4; j++)
                    wmma::store_matrix_sync(st + (i * 16) * 64 + j * 16, acc[i][j], 64,
                                            wmma::mem_row_major);
            __syncwarp();
            int row = blockRow + wm * 32 + lane;
            if (row < M) {
                __half* dst = C + (size_t)row * NHID + wn * 64;
                const float* srow = st + lane * 64;
#pragma unroll
                for (int cc = 0; cc < 64; cc += 8) {
                    float4 f0 = *(const float4*)(srow + cc);
                    float4 f1 = *(const float4*)(srow + cc + 4);
                    uint4 o;
                    __half2 h;
                    h = __floats2half2_rn(f0.x, f0.y); o.x = *(uint32_t*)&h;
                    h = __floats2half2_rn(f0.z, f0.w); o.y = *(uint32_t*)&h;
                    h = __floats2half2_rn(f1.x, f1.y); o.z = *(uint32_t*)&h;
                    h = __floats2half2_rn(f1.z, f1.w); o.w = *(uint32_t*)&h;
                    *(uint4*)(dst + cc) = o;
                }
            }
        }
        __syncthreads();
    }
}

// ---------------------------------------------------------------------------
// CSR build step 1: histogram of destination nodes.
// ---------------------------------------------------------------------------
__global__ __launch_bounds__(256) void hist_kernel(
    const int* __restrict__ dst, int E)
{
    int e = blockIdx.x * blockDim.x + threadIdx.x;
    if (e < E) atomicAdd(&g_cnt[__ldg(dst + e)], 1);
}

// ---------------------------------------------------------------------------
// CSR build step 2: exclusive prefix sum over N counts. Single block, 1024 thr.
// ---------------------------------------------------------------------------
__global__ __launch_bounds__(1024) void scan_kernel(int N)
{
    __shared__ int s[1024];
    int t = threadIdx.x;
    int chunk = (N + 1023) / 1024;
    int beg = t * chunk;
    int end = min(beg + chunk, N);

    int sum = 0;
    for (int i = beg; i < end; i++) sum += g_cnt[i];
    s[t] = sum;
    __syncthreads();

#pragma unroll
    for (int off = 1; off < 1024; off <<= 1) {
        int v = (t >= off) ? s[t - off] : 0;
        __syncthreads();
        s[t] += v;
        __syncthreads();
    }

    int base = s[t] - sum;   // exclusive prefix
    for (int i = beg; i < end; i++) {
        g_rowstart[i] = base;
        g_cursor[i]   = base;
        base += g_cnt[i];
    }
    if (t == 1023) g_rowstart[N] = s[1023];
}

// ---------------------------------------------------------------------------
// CSR build step 3: scatter (src, w) into per-dst segments.
// ---------------------------------------------------------------------------
__global__ __launch_bounds__(256) void scatter_kernel(
    const int* __restrict__ src, const int* __restrict__ dst,
    const float* __restrict__ w, int E)
{
    int e = blockIdx.x * blockDim.x + threadIdx.x;
    if (e >= E) return;
    int d = __ldg(dst + e);
    int pos = atomicAdd(&g_cursor[d], 1);
    g_edges[pos] = make_int2(__ldg(src + e), __float_as_int(__ldg(w + e)));
}

// ---------------------------------------------------------------------------
// Fused SPMM1 + bias + L2 normalize + ReLU. Warp per dst node, CSR gather of
// fp16 rows, fp32 register accumulation (no atomics).
// ---------------------------------------------------------------------------
__global__ __launch_bounds__(256) void spmm1norm_kernel(
    const __half* __restrict__ Hin, const float* __restrict__ b0,
    float* __restrict__ Hout, int M)
{
    int gid = blockIdx.x * blockDim.x + threadIdx.x;
    int node = gid >> 5;
    if (node >= M) return;
    int lane = gid & 31;

    int beg = __ldg(&g_rowstart[node]);
    int end = __ldg(&g_rowstart[node + 1]);

    float4 a0 = make_float4(0.f, 0.f, 0.f, 0.f);
    float4 a1 = make_float4(0.f, 0.f, 0.f, 0.f);

    int i = beg;
    for (; i + 1 < end; i += 2) {
        int2 e0 = __ldg(&g_edges[i]);
        int2 e1 = __ldg(&g_edges[i + 1]);
        half4 v0 = *(const half4*)(Hin + (size_t)e0.x * NHID + lane * 4);
        half4 v1 = *(const half4*)(Hin + (size_t)e1.x * NHID + lane * 4);
        float w0 = __int_as_float(e0.y);
        float w1 = __int_as_float(e1.y);
        float2 f0a = __half22float2(v0.a), f0b = __half22float2(v0.b);
        float2 f1a = __half22float2(v1.a), f1b = __half22float2(v1.b);
        a0.x = fmaf(w0, f0a.x, a0.x); a0.y = fmaf(w0, f0a.y, a0.y);
        a0.z = fmaf(w0, f0b.x, a0.z); a0.w = fmaf(w0, f0b.y, a0.w);
        a1.x = fmaf(w1, f1a.x, a1.x); a1.y = fmaf(w1, f1a.y, a1.y);
        a1.z = fmaf(w1, f1b.x, a1.z); a1.w = fmaf(w1, f1b.y, a1.w);
    }
    if (i < end) {
        int2 e0 = __ldg(&g_edges[i]);
        half4 v0 = *(const half4*)(Hin + (size_t)e0.x * NHID + lane * 4);
        float w0 = __int_as_float(e0.y);
        float2 f0a = __half22float2(v0.a), f0b = __half22float2(v0.b);
        a0.x = fmaf(w0, f0a.x, a0.x); a0.y = fmaf(w0, f0a.y, a0.y);
        a0.z = fmaf(w0, f0b.x, a0.z); a0.w = fmaf(w0, f0b.y, a0.w);
    }

    float4 v;
    float4 b = *(const float4*)(b0 + lane * 4);
    v.x = a0.x + a1.x + b.x;
    v.y = a0.y + a1.y + b.y;
    v.z = a0.z + a1.z + b.z;
    v.w = a0.w + a1.w + b.w;

    float ss = v.x * v.x + v.y * v.y + v.z * v.z + v.w * v.w;
#pragma unroll
    for (int off = 16; off > 0; off >>= 1)
        ss += __shfl_xor_sync(0xffffffffu, ss, off);

    float scale = 1.0f / fmaxf(sqrtf(ss), 1e-12f);

    v.x = fmaxf(v.x * scale, 0.f);
    v.y = fmaxf(v.y * scale, 0.f);
    v.z = fmaxf(v.z * scale, 0.f);
    v.w = fmaxf(v.w * scale, 0.f);
    *(float4*)(Hout + (size_t)node * NHID + lane * 4) = v;
}

// ---------------------------------------------------------------------------
// GEMM2: Z[M,40] = H[M,128] @ W[128,40]. Vectorized LDS.128 both operands.
// Epilogue converts to fp16.
// ---------------------------------------------------------------------------
__global__ __launch_bounds__(256) void gemm2_kernel(
    const float* __restrict__ H, const float* __restrict__ W,
    __half* __restrict__ Z, int M)
{
    __shared__ float hs[128][68];
    __shared__ float wsT[40][68];

    int t = threadIdx.x;
    int node0 = blockIdx.x * 128;
    int ng = t & 31, cg = t >> 5;

    float acc[4][5];
#pragma unroll
    for (int i = 0; i < 4; i++)
#pragma unroll
        for (int j = 0; j < 5; j++) acc[i][j] = 0.f;

#pragma unroll
    for (int h = 0; h < 2; h++) {
        int k0 = h * 64;
        for (int i = t; i < 64 * NCLASS; i += 256) {
            int k = i & 63, c = i >> 6;
            wsT[c][k] = W[(size_t)(k0 + k) * NCLASS + c];
        }

        for (int i = t * 4; i < 128 * 64; i += 256 * 4) {
            int node = i >> 6, k = i & 63;
            int gn = node0 + node;
            float4 v = make_float4(0.f, 0.f, 0.f, 0.f);
            if (gn < M) v = *(const float4*)(H + (size_t)gn * NHID + k0 + k);
            hs[node][k + 0] = v.x;
            hs[node][k + 1] = v.y;
            hs[node][k + 2] = v.z;
            hs[node][k + 3] = v.w;
        }
        __syncthreads();

#pragma unroll 4
        for (int k = 0; k < 64; k += 4) {
            float4 b[5];
#pragma unroll
            for (int j = 0; j < 5; j++) b[j] = *(float4*)&wsT[cg * 5 + j][k];
#pragma unroll
            for (int i = 0; i < 4; i++) {
                float4 a = *(float4*)&hs[ng + 32 * i][k];
#pragma unroll
                for (int j = 0; j < 5; j++) {
                    acc[i][j] = fmaf(a.x, b[j].x, acc[i][j]);
                    acc[i][j] = fmaf(a.y, b[j].y, acc[i][j]);
                    acc[i][j] = fmaf(a.z, b[j].z, acc[i][j]);
                    acc[i][j] = fmaf(a.w, b[j].w, acc[i][j]);
                }
            }
        }
        __syncthreads();
    }

#pragma unroll
    for (int i = 0; i < 4; i++) {
        int gn = node0 + ng + 32 * i;
        if (gn < M)
#pragma unroll
            for (int j = 0; j < 5; j++)
                Z[(size_t)gn * NCLASS + cg * 5 + j] = __float2half_rn(acc[i][j]);
    }
}

// ---------------------------------------------------------------------------
// Fused SPMM2 + bias + log_softmax. Warp per dst node, fp16 CSR gather.
// ---------------------------------------------------------------------------
__global__ __launch_bounds__(256) void spmm2lsm_kernel(
    const __half* __restrict__ Zin, const float* __restrict__ b1,
    float* __restrict__ out, int M)
{
    int gid = blockIdx.x * blockDim.x + threadIdx.x;
    int node = gid >> 5;
    if (node >= M) return;
    int lane = gid & 31;

    int beg = __ldg(&g_rowstart[node]);
    int end = __ldg(&g_rowstart[node + 1]);

    float z0a = 0.f, z0b = 0.f, z1a = 0.f, z1b = 0.f;

    int i = beg;
    for (; i + 1 < end; i += 2) {
        int2 e0 = __ldg(&g_edges[i]);
        int2 e1 = __ldg(&g_edges[i + 1]);
        float w0 = __int_as_float(e0.y);
        float w1 = __int_as_float(e1.y);
        const __half* zr0 = Zin + (size_t)e0.x * NCLASS;
        const __half* zr1 = Zin + (size_t)e1.x * NCLASS;
        z0a = fmaf(w0, __half2float(__ldg(zr0 + lane)), z0a);
        z0b = fmaf(w1, __half2float(__ldg(zr1 + lane)), z0b);
        if (lane < 8) {
            z1a = fmaf(w0, __half2float(__ldg(zr0 + 32 + lane)), z1a);
            z1b = fmaf(w1, __half2float(__ldg(zr1 + 32 + lane)), z1b);
        }
    }
    if (i < end) {
        int2 e0 = __ldg(&g_edges[i]);
        float w0 = __int_as_float(e0.y);
        const __half* zr0 = Zin + (size_t)e0.x * NCLASS;
        z0a = fmaf(w0, __half2float(__ldg(zr0 + lane)), z0a);
        if (lane < 8) z1a = fmaf(w0, __half2float(__ldg(zr0 + 32 + lane)), z1a);
    }

    float z0 = z0a + z0b + __ldg(b1 + lane);
    float z1 = (lane < 8) ? (z1a + z1b + __ldg(b1 + 32 + lane)) : -INFINITY;

    float m = fmaxf(z0, z1);
#pragma unroll
    for (int off = 16; off > 0; off >>= 1)
        m = fmaxf(m, __shfl_xor_sync(0xffffffffu, m, off));

    float es = expf(z0 - m) + ((lane < 8) ? expf(z1 - m) : 0.f);
#pragma unroll
    for (int off = 16; off > 0; off >>= 1)
        es += __shfl_xor_sync(0xffffffffu, es, off);

    float lse = logf(es);
    float* orow = out + (size_t)node * NCLASS;
    orow[lane] = z0 - m - lse;
    if (lane < 8) orow[32 + lane] = z1 - m - lse;
}

// ---------------------------------------------------------------------------
extern "C" void kernel_launch(void* const* d_in, const int* in_sizes, int n_in,
                              void* d_out, int out_size)
{
    const float* x    = (const float*)d_in[0];
    const int*   esrc = (const int*)  d_in[1];
    const int*   edst = (const int*)  d_in[2];
    const float* ew   = (const float*)d_in[3];
    const float* W0   = (const float*)d_in[4];
    const float* b0   = (const float*)d_in[5];
    const float* W1   = (const float*)d_in[6];
    const float* b1   = (const float*)d_in[7];
    float* out = (float*)d_out;

    int M = in_sizes[0] / NFEAT;   // 100000
    int E = in_sizes[1];           // 3200000

    __half *H0p, *Z2p;
    float *H1;
    int* cnt;
    cudaGetSymbolAddress((void**)&H0p, g_H0p);
    cudaGetSymbolAddress((void**)&H1,  g_H1);
    cudaGetSymbolAddress((void**)&Z2p, g_Z2p);
    cudaGetSymbolAddress((void**)&cnt, g_cnt);

    // CSR build
    cudaMemsetAsync(cnt, 0, (size_t)M * sizeof(int), 0);
    hist_kernel<<<(E + 255) / 256, 256>>>(edst, E);
    scan_kernel<<<1, 1024>>>(M);
    scatter_kernel<<<(E + 255) / 256, 256>>>(esrc, edst, ew, E);

    // Layer 1 dense projection via WMMA split-bf16 (fp16 out)
    gemm1_wmma_kernel<<<(M + 127) / 128, 256, G1_SMEM>>>(x, W0, H0p, M);

    // SPMM1 + bias + l2norm + relu (warp/node)
    {
        long long threads = (long long)M * 32;
        spmm1norm_kernel<<<(int)((threads + 255) / 256), 256>>>(H0p, b0, H1, M);
    }

    // Layer 2 dense projection (fp32 -> fp16 out)
    gemm2_kernel<<<(M + 127) / 128, 256>>>(H1, W1, Z2p, M);

    // SPMM2 + bias + log_softmax (warp/node)
    {
        long long threads = (long long)M * 32;
        spmm2lsm_kernel<<<(int)((threads + 255) / 256), 256>>>(Z2p, b1, out, M);
    }
}